// round 16
// baseline (speedup 1.0000x reference)
#include <cuda_runtime.h>
#include <math.h>

// Problem constants
#define B 256
#define N 256
#define D 512
#define EPSV 1e-8f

// Converged champion (R14): DSPLIT=8 (64-d chunks), 256 threads, 2 blocks/SM,
// 256-bit global atoms, parity-staggered batched pass-1.
// Each thread owns an 8-float (32B) column slice and caches 8 rows.
#define DSPLIT 8
#define DCHUNK (D / DSPLIT)   // 64 d's per block
#define DC8 (DCHUNK / 8)      // 8 eight-float columns per block
#define NGROUPS 32
#define NCHUNK (N / NGROUPS)  // 8 n-rows per thread
// block = DC8 * NGROUPS = 256 threads

#define PBF ((N + D) * D)        // new_pd float stride per batch = 393216
#define DIAGF (N * D)            // diag region offset within batch (floats)

// 256-bit global load/store (sm_100+: LDG.E.256 / STG.E.256)
__device__ __forceinline__ void ldg256(const float* p, float* f) {
    asm volatile("ld.global.nc.v8.f32 {%0,%1,%2,%3,%4,%5,%6,%7}, [%8];"
                 : "=f"(f[0]), "=f"(f[1]), "=f"(f[2]), "=f"(f[3]),
                   "=f"(f[4]), "=f"(f[5]), "=f"(f[6]), "=f"(f[7])
                 : "l"(p));
}
__device__ __forceinline__ void stg256(float* p, const float* f) {
    asm volatile("st.global.v8.f32 [%0], {%1,%2,%3,%4,%5,%6,%7,%8};"
                 :: "l"(p), "f"(f[0]), "f"(f[1]), "f"(f[2]), "f"(f[3]),
                    "f"(f[4]), "f"(f[5]), "f"(f[6]), "f"(f[7])
                 : "memory");
}

// Register-cached mega-kernel, 256-bit atom variant with parity-staggered
// pass-1 (co-resident blocks start in opposite read/write phases, so the SM
// presents a mixed read/write stream to DRAM; batched loads keep MLP=8).
//  Pass 1: 8 x LDG.256 slice loads + 16 x STG.256 diag zero-fill
//          (order by blockIdx parity), then abs-sum.
//  Reduce: lam/beta/delta per d (cv/err prefetched); write new_central /
//          new_err; patch 64 diagonal scalars (ordered by barrier 1).
//  Pass 2: scale register-resident values, 8 x STG.256 scaled_pd.
//  pd is read from DRAM exactly once.
__global__ __launch_bounds__(256, 2) void k_mega(const float* __restrict__ cv,
                                                 const float* __restrict__ pd,
                                                 const float* __restrict__ err,
                                                 float* __restrict__ out_central,
                                                 float* __restrict__ out_pd,
                                                 float* __restrict__ out_err) {
    const int b = blockIdx.x;
    const int h = blockIdx.y;        // d-chunk index, 0..7
    const int tid = threadIdx.x;
    const int d8 = tid & (DC8 - 1);  // 0..7  (32B column within chunk)
    const int g = tid >> 3;          // 0..31 (n-group)

    __shared__ float s_acc[NGROUPS][DC8][9];  // pad to 9: conflict-free
    __shared__ float s_lam[DCHUNK];

    // Base pointer for this thread's 8-float column of the pd slice
    const float* p = pd + (size_t)b * N * D + (size_t)(g * NCHUNK) * D
                     + h * DCHUNK + d8 * 8;

    // Diag share of this block: rows [h*64, h*64+64) of batch b
    // = 64 rows * 512 floats = 4096 x 32B vectors.
    float* diag_blk = out_pd + (size_t)b * PBF + DIAGF + (size_t)h * DCHUNK * D;
    float zv[8] = {0.f, 0.f, 0.f, 0.f, 0.f, 0.f, 0.f, 0.f};

    // Prefetch cv/err for the reduction threads (hidden behind pass 1).
    const int dg = h * DCHUNK + tid;     // global d index (valid for tid<64)
    const int bd = b * D + dg;
    float e_pf = 0.f, c_pf = 0.f;
    if (tid < DCHUNK) {
        e_pf = err[bd];
        c_pf = cv[bd];
    }

    float v[NCHUNK][8];
    if (b & 1) {
        // Odd blocks: zero-fill stores first, then loads.
#pragma unroll
        for (int n = 0; n < NCHUNK; n++) {
            stg256(diag_blk + (size_t)(n * 512 + tid) * 8, zv);
            stg256(diag_blk + (size_t)(n * 512 + 256 + tid) * 8, zv);
        }
#pragma unroll
        for (int n = 0; n < NCHUNK; n++)
            ldg256(p + (size_t)n * D, v[n]);
    } else {
        // Even blocks: loads first, then zero-fill stores.
#pragma unroll
        for (int n = 0; n < NCHUNK; n++)
            ldg256(p + (size_t)n * D, v[n]);
#pragma unroll
        for (int n = 0; n < NCHUNK; n++) {
            stg256(diag_blk + (size_t)(n * 512 + tid) * 8, zv);
            stg256(diag_blk + (size_t)(n * 512 + 256 + tid) * 8, zv);
        }
    }

    // Abs-sum over this thread's 8 rows
    float acc[8] = {0.f, 0.f, 0.f, 0.f, 0.f, 0.f, 0.f, 0.f};
#pragma unroll
    for (int n = 0; n < NCHUNK; n++) {
#pragma unroll
        for (int k = 0; k < 8; k++)
            acc[k] += fabsf(v[n][k]);
    }
#pragma unroll
    for (int k = 0; k < 8; k++)
        s_acc[g][d8][k] = acc[k];
    __syncthreads();  // barrier 1

    // Combine groups + compute lam/beta/delta: threads 0..63, one d each
    if (tid < DCHUNK) {
        const int dc8 = tid >> 3;
        const int lane = tid & 7;
        float r = 0.f;
#pragma unroll
        for (int gg = 0; gg < NGROUPS; gg++)
            r += s_acc[gg][dc8][lane];

        const float e = e_pf;
        const float c = c_pf;

        const float radius = r + fabsf(e);
        const float lower = c - radius;
        const float upper = c + radius;
        const float rl = fmaxf(lower, 0.f);
        const float ru = fmaxf(upper, 0.f);

        float lam = (ru - rl) / (upper - lower + EPSV);
        if (lower >= 0.f) lam = 1.f;
        if (upper < 0.f) lam = 0.f;
        if (isnan(lam)) lam = 0.f;
        lam = fminf(fmaxf(lam, 0.f), 1.f);

        const float beta = (rl - lam * lower) * 0.5f;
        const float delta = fabsf(beta);

        out_central[bd] = lam * c + beta;
        out_err[bd] = lam * e;

        // Patch diagonal: local diag row tid has its element at global col dg.
        // Ordered after the zero-fill by barrier 1.
        diag_blk[(size_t)tid * D + dg] = delta;

        s_lam[tid] = lam;
    }
    __syncthreads();  // barrier 2

    // Pass 2: scale register-resident values and store scaled_pd.
    // new_pd layout: (B, N+D, D); rows [0, N) are scaled_pd.
    float lamv[8];
#pragma unroll
    for (int k = 0; k < 8; k++)
        lamv[k] = s_lam[d8 * 8 + k];

    float* o = out_pd + (size_t)b * PBF + (size_t)(g * NCHUNK) * D
               + h * DCHUNK + d8 * 8;
#pragma unroll
    for (int n = 0; n < NCHUNK; n++) {
        float w[8];
#pragma unroll
        for (int k = 0; k < 8; k++)
            w[k] = v[n][k] * lamv[k];
        stg256(o + (size_t)n * D, w);
    }
}

extern "C" void kernel_launch(void* const* d_in, const int* in_sizes, int n_in,
                              void* d_out, int out_size) {
    const float* cv = (const float*)d_in[0];   // (256, 512)
    const float* pd = (const float*)d_in[1];   // (256, 256, 512)
    const float* err = (const float*)d_in[2];  // (256, 512)

    float* out = (float*)d_out;
    // Output layout: [new_central (B*D)] [new_pd (B*(N+D)*D)] [new_err (B*D)]
    float* out_central = out;
    float* out_pd = out + (size_t)B * D;
    float* out_err = out + (size_t)B * D + (size_t)B * (N + D) * D;

    dim3 grid(B, DSPLIT);  // 2048 blocks of 256 threads
    k_mega<<<grid, 256>>>(cv, pd, err, out_central, out_pd, out_err);
}

// round 17
// speedup vs baseline: 1.0234x; 1.0234x over previous
#include <cuda_runtime.h>
#include <math.h>

// Problem constants
#define B 256
#define N 256
#define D 512
#define EPSV 1e-8f

// Final converged kernel (R13, best measured total 86.40 us):
// DSPLIT=8 (64-d chunks), 256 threads, 2 blocks/SM, 16-float4 register cache
// per thread (MLP=16), parity-staggered pass-1, cv/err prefetch.
#define DSPLIT 8
#define DCHUNK (D / DSPLIT)   // 64 d's per block
#define DC4 (DCHUNK / 4)      // 16 float4 columns per block
#define NGROUPS 16
#define NCHUNK (N / NGROUPS)  // 16 n-rows per thread
// block = DC4 * NGROUPS = 256 threads

#define D4 (D / 4)               // 128
#define PB4 ((N + D) * D4)       // new_pd float4 stride per batch = 98304
#define DIAG4 (N * D4)           // diag region offset within batch = 32768

// Register-cached mega-kernel with PARITY-STAGGERED pass-1: the two
// co-resident blocks per SM start in opposite phases (one issuing its diag
// zero-fill stores while the other issues its slice loads), presenting a
// steady mixed read/write stream to DRAM.
//  Pass 1 (order by blockIdx parity):
//    - 32 independent diag zero-fill STG.128
//    - front-batched 16 slice LDG.128 (MLP=16)
//    then abs-sum FMAs.
//  Reduce: lam/beta/delta per d (cv/err prefetched before barrier 1);
//          write new_central/new_err; patch 64 diagonal scalars.
//  Pass 2: scale register-resident values, store scaled_pd.
//  pd is read from DRAM exactly once.
__global__ __launch_bounds__(256, 2) void k_mega(const float* __restrict__ cv,
                                                 const float4* __restrict__ pd4,
                                                 const float* __restrict__ err,
                                                 float* __restrict__ out_central,
                                                 float4* __restrict__ out_pd4,
                                                 float* __restrict__ out_err) {
    const int b = blockIdx.x;
    const int h = blockIdx.y;        // d-chunk index, 0..7
    const int tid = threadIdx.x;
    const int d4 = tid & (DC4 - 1);  // 0..15 (float4 column within chunk)
    const int g = tid >> 4;          // 0..15 (n-group)

    __shared__ float4 s_acc[NGROUPS][DC4];
    __shared__ float4 s_lam[DC4];

    // Base pointer for this thread's float4 column of the pd slice
    const float4* p = pd4 + (size_t)b * N * D4 + (size_t)(g * NCHUNK) * D4
                      + h * DC4 + d4;

    // Diag share of this block: rows [h*64, h*64+64) of batch b
    // = 64 rows * 128 float4 = 8192 float4.
    float4* diag_blk = out_pd4 + (size_t)b * PB4 + DIAG4 + (size_t)h * DCHUNK * D4;
    const float4 z = make_float4(0.f, 0.f, 0.f, 0.f);

    // Prefetch cv/err for the reduction threads (hidden behind pass 1).
    const int dg = h * DCHUNK + tid;     // global d index (valid for tid<64)
    const int bd = b * D + dg;
    float e_pf = 0.f, c_pf = 0.f;
    if (tid < DCHUNK) {
        e_pf = err[bd];
        c_pf = cv[bd];
    }

    float4 v[NCHUNK];
    if (b & 1) {
        // Odd blocks: stores first, then loads.
#pragma unroll
        for (int n = 0; n < NCHUNK; n++) {
            diag_blk[n * 512 + tid] = z;
            diag_blk[n * 512 + 256 + tid] = z;
        }
#pragma unroll
        for (int n = 0; n < NCHUNK; n++)
            v[n] = p[(size_t)n * D4];
    } else {
        // Even blocks: loads first, then stores.
#pragma unroll
        for (int n = 0; n < NCHUNK; n++)
            v[n] = p[(size_t)n * D4];
#pragma unroll
        for (int n = 0; n < NCHUNK; n++) {
            diag_blk[n * 512 + tid] = z;
            diag_blk[n * 512 + 256 + tid] = z;
        }
    }

    // Abs-sum
    float4 acc = make_float4(0.f, 0.f, 0.f, 0.f);
#pragma unroll
    for (int n = 0; n < NCHUNK; n++) {
        acc.x += fabsf(v[n].x);
        acc.y += fabsf(v[n].y);
        acc.z += fabsf(v[n].z);
        acc.w += fabsf(v[n].w);
    }
    s_acc[g][d4] = acc;
    __syncthreads();  // barrier 1

    // Combine groups + compute lam/beta/delta: threads 0..63, one d each
    if (tid < DCHUNK) {
        const int dc4 = tid >> 2;
        const int lane = tid & 3;
        float r = 0.f;
#pragma unroll
        for (int gg = 0; gg < NGROUPS; gg++)
            r += ((const float*)&s_acc[gg][dc4])[lane];

        const float e = e_pf;
        const float c = c_pf;

        const float radius = r + fabsf(e);
        const float lower = c - radius;
        const float upper = c + radius;
        const float rl = fmaxf(lower, 0.f);
        const float ru = fmaxf(upper, 0.f);

        float lam = (ru - rl) / (upper - lower + EPSV);
        if (lower >= 0.f) lam = 1.f;
        if (upper < 0.f) lam = 0.f;
        if (isnan(lam)) lam = 0.f;
        lam = fminf(fmaxf(lam, 0.f), 1.f);

        const float beta = (rl - lam * lower) * 0.5f;
        const float delta = fabsf(beta);

        out_central[bd] = lam * c + beta;
        out_err[bd] = lam * e;

        // Patch diagonal: local diag row tid has its element at global col dg.
        // Ordered after the zero-fill by barrier 1.
        ((float*)diag_blk)[(size_t)tid * D + dg] = delta;

        ((float*)&s_lam[dc4])[lane] = lam;
    }
    __syncthreads();  // barrier 2

    // Pass 2: scale register-resident values and store scaled_pd.
    // new_pd layout: (B, N+D, D); rows [0, N) are scaled_pd.
    const float4 lam4 = s_lam[d4];
    float4* o = out_pd4 + (size_t)b * PB4 + (size_t)(g * NCHUNK) * D4
                + h * DC4 + d4;
#pragma unroll
    for (int n = 0; n < NCHUNK; n++) {
        float4 w;
        w.x = v[n].x * lam4.x;
        w.y = v[n].y * lam4.y;
        w.z = v[n].z * lam4.z;
        w.w = v[n].w * lam4.w;
        o[(size_t)n * D4] = w;
    }
}

extern "C" void kernel_launch(void* const* d_in, const int* in_sizes, int n_in,
                              void* d_out, int out_size) {
    const float* cv = (const float*)d_in[0];   // (256, 512)
    const float* pd = (const float*)d_in[1];   // (256, 256, 512)
    const float* err = (const float*)d_in[2];  // (256, 512)

    float* out = (float*)d_out;
    // Output layout: [new_central (B*D)] [new_pd (B*(N+D)*D)] [new_err (B*D)]
    float* out_central = out;
    float* out_pd = out + (size_t)B * D;
    float* out_err = out + (size_t)B * D + (size_t)B * (N + D) * D;

    dim3 grid(B, DSPLIT);  // 2048 blocks of 256 threads
    k_mega<<<grid, 256>>>(cv, (const float4*)pd, err,
                          out_central, (float4*)out_pd, out_err);
}